// round 1
// baseline (speedup 1.0000x reference)
#include <cuda_runtime.h>
#include <cuda_bf16.h>
#include <math.h>

#define BB 32
#define DD 8732
#define OO 8
#define CC 21
#define LL 32
#define KK 256

// ---------------- device scratch (static, no allocation) ----------------
__device__ float  d_prov[BB*DD];
__device__ int    d_pidx[BB*DD];
__device__ int    d_conf[BB*DD];
__device__ float  d_loct[BB*DD*4];
__device__ float  d_poset[BB*DD*3];
__device__ float  d_ceneg[BB*DD];
__device__ int    d_numpos[BB];
__device__ int    d_off[BB+1];

__device__ double a_lossl, a_lossc, a_lossp, a_desk, a_trips;
__device__ unsigned long long a_npp, a_nnp, a_tripc;

__device__ float  d_emb[KK*LL];
__device__ int    d_lab[KK];
__device__ float  d_qp[KK*3];
__device__ int    d_val[KK];
__device__ float  d_dist[KK*KK];
__device__ unsigned d_pm[KK*8];
__device__ unsigned d_nm[KK*8];

// ---------------- kernels ----------------
__global__ void k_init() {
    if (threadIdx.x == 0 && blockIdx.x == 0) {
        a_lossl = 0.0; a_lossc = 0.0; a_lossp = 0.0; a_desk = 0.0; a_trips = 0.0;
        a_npp = 0ull; a_nnp = 0ull; a_tripc = 0ull;
    }
}

// One block per batch: matching + encode + loc/pose losses.
__global__ void k_match(const float* __restrict__ loc,
                        const float* __restrict__ pose,
                        const float* __restrict__ dbox,
                        const float* __restrict__ tgt) {
    const int b = blockIdx.x;
    const int tid = threadIdx.x;
    const int T = blockDim.x; // 256

    __shared__ float tx1[OO], ty1[OO], tx2[OO], ty2[OO], ta[OO];
    __shared__ float tpz[OO][3];
    __shared__ int   tlab[OO];
    if (tid < OO) {
        const float* p = tgt + (size_t)(b*OO + tid)*9;
        tx1[tid] = p[0]; ty1[tid] = p[1]; tx2[tid] = p[2]; ty2[tid] = p[3];
        ta[tid]  = (p[2]-p[0])*(p[3]-p[1]);
        tlab[tid] = (int)p[4];
        tpz[tid][0] = p[5]; tpz[tid][1] = p[6]; tpz[tid][2] = p[7];
    }
    __syncthreads();

    float bv[OO]; int bd[OO];
#pragma unroll
    for (int t = 0; t < OO; t++) { bv[t] = -1.0f; bd[t] = 0x7fffffff; }

    for (int d = tid; d < DD; d += T) {
        float cx = dbox[d*4+0], cy = dbox[d*4+1], w = dbox[d*4+2], h = dbox[d*4+3];
        float px1 = cx - w*0.5f, py1 = cy - h*0.5f;
        float px2 = cx + w*0.5f, py2 = cy + h*0.5f;
        float pa = (px2-px1)*(py2-py1);
        float mv = -1.0f; int mt = 0;
#pragma unroll
        for (int t = 0; t < OO; t++) {
            float ix = fmaxf(fminf(tx2[t], px2) - fmaxf(tx1[t], px1), 0.0f);
            float iy = fmaxf(fminf(ty2[t], py2) - fmaxf(ty1[t], py1), 0.0f);
            float inter = ix * iy;
            float iou = inter / (ta[t] + pa - inter);
            if (iou > mv) { mv = iou; mt = t; }          // first-occurrence over t
            if (iou > bv[t]) { bv[t] = iou; bd[t] = d; } // ascending d per thread
        }
        d_prov[b*DD + d] = mv;
        d_pidx[b*DD + d] = mt;
    }

    // reduce per-truth best prior (max value, tie -> min index)
    __shared__ float sv[256];
    __shared__ int   sd[256];
    __shared__ int   bestp[OO];
    for (int t = 0; t < OO; t++) {
        sv[tid] = bv[t]; sd[tid] = bd[t];
        __syncthreads();
        for (int s = T/2; s > 0; s >>= 1) {
            if (tid < s) {
                float v2 = sv[tid+s]; int d2 = sd[tid+s];
                if (v2 > sv[tid] || (v2 == sv[tid] && d2 < sd[tid])) { sv[tid] = v2; sd[tid] = d2; }
            }
            __syncthreads();
        }
        if (tid == 0) bestp[t] = sd[0];
        __syncthreads();
    }

    if (tid == 0) {
        for (int t = 0; t < OO; t++) {   // sequential t-order (scatter last-wins)
            int d = bestp[t];
            d_prov[b*DD + d] = 2.0f;
            d_pidx[b*DD + d] = t;
        }
    }
    __syncthreads();

    // pass 2: conf_t, encode, losses
    double ll = 0.0, lp = 0.0; int np = 0;
    for (int d = tid; d < DD; d += T) {
        int idx = b*DD + d;
        int t = d_pidx[idx];
        float ov = d_prov[idx];
        int cf = (ov < 0.5f) ? 0 : (tlab[t] + 1);
        d_conf[idx] = cf;

        float cx = dbox[d*4+0], cy = dbox[d*4+1], w = dbox[d*4+2], h = dbox[d*4+3];
        float g0 = ((tx1[t] + tx2[t])*0.5f - cx) / (0.1f * w);
        float g1 = ((ty1[t] + ty2[t])*0.5f - cy) / (0.1f * h);
        float g2 = logf((tx2[t] - tx1[t]) / w) / 0.2f;
        float g3 = logf((ty2[t] - ty1[t]) / h) / 0.2f;
        d_loct[idx*4+0] = g0; d_loct[idx*4+1] = g1;
        d_loct[idx*4+2] = g2; d_loct[idx*4+3] = g3;
        d_poset[idx*3+0] = tpz[t][0];
        d_poset[idx*3+1] = tpz[t][1];
        d_poset[idx*3+2] = tpz[t][2];

        if (cf > 0) {
            np++;
            float g[4] = {g0, g1, g2, g3};
#pragma unroll
            for (int i = 0; i < 4; i++) {
                float dd_ = loc[(size_t)idx*4 + i] - g[i];
                float ad = fabsf(dd_);
                ll += (double)((ad < 1.0f) ? (0.5f*dd_*dd_) : (ad - 0.5f));
            }
#pragma unroll
            for (int i = 0; i < 3; i++) {
                float e = pose[(size_t)idx*3 + i] - tpz[t][i];
                lp += (double)(e*e);
            }
        }
    }

    __shared__ double sll[256], slp[256];
    __shared__ int    snp[256];
    sll[tid] = ll; slp[tid] = lp; snp[tid] = np;
    __syncthreads();
    for (int s = T/2; s > 0; s >>= 1) {
        if (tid < s) { sll[tid] += sll[tid+s]; slp[tid] += slp[tid+s]; snp[tid] += snp[tid+s]; }
        __syncthreads();
    }
    if (tid == 0) {
        d_numpos[b] = snp[0];
        atomicAdd(&a_lossl, sll[0]);
        atomicAdd(&a_lossp, slp[0]);
    }
}

// CE per prior; positives summed into loss_c, negatives stored for mining.
__global__ void k_ce(const float* __restrict__ conf) {
    int b = blockIdx.y;
    int d = blockIdx.x * blockDim.x + threadIdx.x;
    double pce = 0.0;
    if (d < DD) {
        int idx = b*DD + d;
        const float* x = conf + (size_t)idx * CC;
        float m = x[0];
#pragma unroll
        for (int c = 1; c < CC; c++) m = fmaxf(m, x[c]);
        float s = 0.0f;
#pragma unroll
        for (int c = 0; c < CC; c++) s += expf(x[c] - m);
        float lse = m + logf(s);
        int ct = d_conf[idx];
        float ce = lse - x[ct];
        if (ct > 0) { d_ceneg[idx] = 0.0f; pce = (double)ce; }
        else        { d_ceneg[idx] = ce; }
    }
    __shared__ double sp[256];
    sp[threadIdx.x] = pce;
    __syncthreads();
    for (int s = 128; s > 0; s >>= 1) {
        if (threadIdx.x < s) sp[threadIdx.x] += sp[threadIdx.x + s];
        __syncthreads();
    }
    if (threadIdx.x == 0 && sp[0] != 0.0) atomicAdd(&a_lossc, sp[0]);
}

// Exact top-k sum per batch via 32-pass radix select (keys: non-negative f32 bits).
__global__ void k_topk() {
    int b = blockIdx.x, tid = threadIdx.x;
    const int T = blockDim.x;
    int k = d_numpos[b] * 3;
    if (k > DD) k = DD;
    if (k <= 0) return;
    const float* ce = d_ceneg + (size_t)b * DD;

    __shared__ int s_cnt[256];
    __shared__ unsigned s_pref;
    __shared__ int s_rem;
    if (tid == 0) { s_pref = 0u; s_rem = k; }
    __syncthreads();

    for (int bit = 31; bit >= 0; bit--) {
        unsigned pref = s_pref;
        int c = 0;
        for (int d = tid; d < DD; d += T) {
            unsigned u = __float_as_uint(ce[d]);
            bool hi = (bit == 31) ? true : ((u >> (bit+1)) == (pref >> (bit+1)));
            if (hi && ((u >> bit) & 1u)) c++;
        }
        s_cnt[tid] = c;
        __syncthreads();
        for (int s = T/2; s > 0; s >>= 1) {
            if (tid < s) s_cnt[tid] += s_cnt[tid+s];
            __syncthreads();
        }
        if (tid == 0) {
            if (s_cnt[0] >= s_rem) s_pref = pref | (1u << bit);
            else s_rem -= s_cnt[0];
        }
        __syncthreads();
    }

    unsigned uT = s_pref;
    float Tv = __uint_as_float(uT);
    double sg = 0.0; int cg = 0;
    for (int d = tid; d < DD; d += T) {
        float v = ce[d];
        if (__float_as_uint(v) > uT) { sg += (double)v; cg++; }
    }
    __shared__ double sdb[256];
    sdb[tid] = sg; s_cnt[tid] = cg;
    __syncthreads();
    for (int s = T/2; s > 0; s >>= 1) {
        if (tid < s) { sdb[tid] += sdb[tid+s]; s_cnt[tid] += s_cnt[tid+s]; }
        __syncthreads();
    }
    if (tid == 0) {
        double contrib = sdb[0] + (double)(k - s_cnt[0]) * (double)Tv;
        atomicAdd(&a_lossc, contrib);
    }
}

__global__ void k_off() {
    if (threadIdx.x == 0 && blockIdx.x == 0) {
        int acc = 0;
        for (int b = 0; b < BB; b++) { d_off[b] = acc; acc += d_numpos[b]; }
        d_off[BB] = acc;
    }
}

// Ordered compaction: positives in flat order, then earliest negatives (all in batch 0, d<256).
__global__ void k_compact(const float* __restrict__ line) {
    int b = blockIdx.x, tid = threadIdx.x;
    const int CH = (DD + 255) / 256; // 35
    int d0 = tid * CH;
    int d1 = d0 + CH; if (d1 > DD) d1 = DD;

    int cnt = 0;
    for (int d = d0; d < d1; d++) if (d_conf[b*DD + d] > 0) cnt++;
    __shared__ int sc[256];
    sc[tid] = cnt;
    __syncthreads();
    if (tid == 0) {
        int acc = 0;
        for (int i = 0; i < 256; i++) { int c = sc[i]; sc[i] = acc; acc += c; }
    }
    __syncthreads();

    int rank = d_off[b] + sc[tid];
    for (int d = d0; d < d1 && rank < KK; d++) {
        int idx = b*DD + d;
        if (d_conf[idx] > 0) {
            int slot = rank++;
            d_lab[slot] = d_conf[idx];
            d_val[slot] = 1;
#pragma unroll
            for (int l = 0; l < LL; l++) d_emb[slot*LL + l] = line[(size_t)idx*LL + l];
            d_qp[slot*3+0] = d_poset[idx*3+0];
            d_qp[slot*3+1] = d_poset[idx*3+1];
            d_qp[slot*3+2] = d_poset[idx*3+2];
        }
    }

    if (b == 0) {
        __syncthreads();
        __shared__ int smap[256];
        if (tid == 0) {
            int Pt = d_off[BB];
            int nr = 0;
            for (int d = 0; d < 256; d++) {
                int slot = -1;
                if (d_conf[d] == 0) {
                    int s2 = Pt + nr; nr++;
                    if (s2 < KK) slot = s2;
                }
                smap[d] = slot;
            }
        }
        __syncthreads();
        int d = tid; // one thread per flat index < 256
        int slot = smap[d];
        if (slot >= 0) {
            d_lab[slot] = d_conf[d];
            d_val[slot] = 0;
#pragma unroll
            for (int l = 0; l < LL; l++) d_emb[slot*LL + l] = line[(size_t)d*LL + l];
            d_qp[slot*3+0] = d_poset[d*3+0];
            d_qp[slot*3+1] = d_poset[d*3+1];
            d_qp[slot*3+2] = d_poset[d*3+2];
        }
    }
}

// Pairwise distances, pair masks, desk sum, pair counts. Block i, thread j.
__global__ void k_pairs() {
    int i = blockIdx.x, j = threadIdx.x;
    __shared__ float ei[LL], ni[LL], qi[3];
    __shared__ int labi, vali;
    if (j < LL) ei[j] = d_emb[i*LL + j];
    if (j == 0) {
        labi = d_lab[i]; vali = d_val[i];
        qi[0] = d_qp[i*3+0]; qi[1] = d_qp[i*3+1]; qi[2] = d_qp[i*3+2];
    }
    __syncthreads();
    if (j == 0) {
        float s = 0.0f;
        for (int l = 0; l < LL; l++) s += ei[l]*ei[l];
        float n = fmaxf(sqrtf(s), 1e-12f);
        for (int l = 0; l < LL; l++) ni[l] = ei[l] / n;
    }
    __syncthreads();

    float ej[LL];
#pragma unroll
    for (int l = 0; l < LL; l++) ej[l] = d_emb[j*LL + l];
    float s = 0.0f;
#pragma unroll
    for (int l = 0; l < LL; l++) s += ej[l]*ej[l];
    float nj = fmaxf(sqrtf(s), 1e-12f);

    float sq = 0.0f, esq = 0.0f;
#pragma unroll
    for (int l = 0; l < LL; l++) {
        float dn = ni[l] - ej[l]/nj; sq  += dn*dn;
        float de = ei[l] - ej[l];    esq += de*de;
    }
    float dist = sqrtf(fmaxf(sq, 1e-12f));
    d_dist[i*KK + j] = dist;

    float qsq = 0.0f;
#pragma unroll
    for (int c = 0; c < 3; c++) { float dq = qi[c] - d_qp[j*3+c]; qsq += dq*dq; }

    bool vp   = vali && d_val[j] && (i != j);
    bool same = (labi == d_lab[j]);
    bool pp = vp &&  same && (dist > 0.2f);
    bool np = vp && !same && (dist < 0.8f);

    unsigned pb = __ballot_sync(0xffffffffu, pp);
    unsigned nb = __ballot_sync(0xffffffffu, np);
    if ((j & 31) == 0) { d_pm[i*8 + (j>>5)] = pb; d_nm[i*8 + (j>>5)] = nb; }

    double dk = pp ? (double)((esq - qsq) * (esq - qsq)) : 0.0;
    __shared__ double sdk[256];
    __shared__ int spp[256], snn[256];
    sdk[j] = dk; spp[j] = pp ? 1 : 0; snn[j] = np ? 1 : 0;
    __syncthreads();
    for (int st = 128; st > 0; st >>= 1) {
        if (j < st) { sdk[j] += sdk[j+st]; spp[j] += spp[j+st]; snn[j] += snn[j+st]; }
        __syncthreads();
    }
    if (j == 0) {
        if (sdk[0] != 0.0) atomicAdd(&a_desk, sdk[0]);
        if (spp[0]) atomicAdd(&a_npp, (unsigned long long)spp[0]);
        if (snn[0]) atomicAdd(&a_nnp, (unsigned long long)snn[0]);
    }
}

// Triplet loss: block i (anchor), thread k (negative partner), loop over positives j.
__global__ void k_trip() {
    int i = blockIdx.x, tid = threadIdx.x;
    __shared__ float sdist[KK];
    __shared__ unsigned pm[8], nm[8];
    sdist[tid] = d_dist[i*KK + tid];
    if (tid < 8) { pm[tid] = d_pm[i*8 + tid]; nm[tid] = d_nm[i*8 + tid]; }
    __syncthreads();

    __shared__ int pj[KK];
    __shared__ int npj;
    if (tid == 0) {
        int n = 0;
        for (int w = 0; w < 8; w++) {
            unsigned m = pm[w];
            while (m) { int bpos = __ffs(m) - 1; pj[n++] = w*32 + bpos; m &= (m - 1); }
        }
        npj = n;
    }
    __syncthreads();
    int n = npj;
    if (n == 0) return;

    bool isneg = (nm[tid >> 5] >> (tid & 31)) & 1u;
    double ls = 0.0;
    unsigned long long lc = 0ull;
    if (isneg) {
        float dk = sdist[tid];
        for (int a = 0; a < n; a++) {
            float l = sdist[pj[a]] - dk + 0.2f;
            if (l > 0.0f) { ls += (double)l; lc++; }
        }
    }
    __shared__ double rs[256];
    __shared__ unsigned long long rc[256];
    rs[tid] = ls; rc[tid] = lc;
    __syncthreads();
    for (int s = 128; s > 0; s >>= 1) {
        if (tid < s) { rs[tid] += rs[tid+s]; rc[tid] += rc[tid+s]; }
        __syncthreads();
    }
    if (tid == 0 && (rs[0] != 0.0 || rc[0] != 0ull)) {
        atomicAdd(&a_trips, rs[0]);
        atomicAdd(&a_tripc, rc[0]);
    }
}

__global__ void k_final(float* __restrict__ out) {
    if (threadIdx.x == 0 && blockIdx.x == 0) {
        double N = (double)d_off[BB];
        if (N < 1.0) N = 1.0;
        double lossl = a_lossl / N;
        double lossc = a_lossc / N;
        double lossp = a_lossp / N;

        unsigned long long npp = a_npp;
        double dnpp = (npp < 1ull) ? 1.0 : (double)npp;
        unsigned long long tc = a_tripc;
        double losst = a_trips / (double)((tc < 1ull) ? 1ull : tc);
        unsigned long long pn = a_npp + a_nnp;
        double dpn = (pn < 1ull) ? 1.0 : (double)pn;

        double ldesk = a_desk / dnpp + losst / dpn;
        ldesk = ldesk / dnpp / 32.0;

        out[0] = (float)lossl;
        out[1] = (float)lossc;
        out[2] = (float)lossp;
        out[3] = (float)ldesk;
        out[4] = (float)losst;
    }
}

// ---------------- host launcher ----------------
extern "C" void kernel_launch(void* const* d_in, const int* in_sizes, int n_in,
                              void* d_out, int out_size) {
    const float *loc = 0, *conf = 0, *line = 0, *pose = 0, *dbox = 0, *tgt = 0;
    for (int i = 0; i < n_in; i++) {
        switch (in_sizes[i]) {
            case BB*DD*4:  loc  = (const float*)d_in[i]; break; // 1117696
            case BB*DD*CC: conf = (const float*)d_in[i]; break; // 5867904
            case BB*DD*LL: line = (const float*)d_in[i]; break; // 8941568
            case BB*DD*3:  pose = (const float*)d_in[i]; break; // 838272
            case DD*4:     dbox = (const float*)d_in[i]; break; // 34928
            case BB*OO*9:  tgt  = (const float*)d_in[i]; break; // 2304
            default: break;
        }
    }
    // positional fallback (reference signature order)
    if (!loc)  loc  = (const float*)d_in[0];
    if (!conf) conf = (const float*)d_in[1];
    if (!line) line = (const float*)d_in[2];
    if (!pose) pose = (const float*)d_in[3];
    if (!dbox) dbox = (const float*)d_in[4];
    if (!tgt)  tgt  = (const float*)d_in[5];

    k_init<<<1, 32>>>();
    k_match<<<BB, 256>>>(loc, pose, dbox, tgt);
    k_ce<<<dim3((DD + 255) / 256, BB), 256>>>(conf);
    k_topk<<<BB, 256>>>();
    k_off<<<1, 1>>>();
    k_compact<<<BB, 256>>>(line);
    k_pairs<<<KK, 256>>>();
    k_trip<<<KK, 256>>>();
    k_final<<<1, 1>>>((float*)d_out);
}

// round 2
// speedup vs baseline: 1.9639x; 1.9639x over previous
#include <cuda_runtime.h>
#include <cuda_bf16.h>
#include <math.h>

#define BB 32
#define DD 8732
#define OO 8
#define CC 21
#define LL 32
#define KK 256
#define NCH 8
#define CH  1092   // NCH*CH = 8736 >= DD

// ---------------- device scratch (static, no allocation) ----------------
__device__ float  d_prov[BB*DD];
__device__ int    d_pidx[BB*DD];
__device__ int    d_conf[BB*DD];
__device__ float  d_ceneg[BB*DD];
__device__ int    d_numpos[BB];
__device__ unsigned long long d_bestkey[BB*OO];

__device__ double a_lossl, a_lossc, a_lossp, a_desk, a_trips;
__device__ unsigned long long a_npp, a_nnp, a_tripc;

__device__ float  d_emb[KK*LL];
__device__ int    d_lab[KK];
__device__ float  d_qp[KK*3];
__device__ int    d_val[KK];
__device__ float  d_dist[KK*KK];
__device__ unsigned d_pm[KK*8];
__device__ unsigned d_nm[KK*8];

// fast exp on the FMA pipe (valid for x in ~[-80, 0]; inputs are x - max <= 0)
__device__ __forceinline__ float fexp(float x) {
    x = fmaxf(x, -80.0f);
    float y = x * 1.442695040888963f;
    float n = rintf(y);
    float f = y - n;                       // [-0.5, 0.5]
    float p = 1.54035303933816e-4f;        // 2^f Taylor (ln2 powers), deg 6
    p = fmaf(p, f, 1.33335581464284e-3f);
    p = fmaf(p, f, 9.61812910762848e-3f);
    p = fmaf(p, f, 5.55041086648216e-2f);
    p = fmaf(p, f, 2.40226506959101e-1f);
    p = fmaf(p, f, 6.93147180559945e-1f);
    p = fmaf(p, f, 1.0f);
    return __int_as_float(__float_as_int(p) + (((int)n) << 23));
}

// ---------------- kernels ----------------
__global__ void k_init() {
    int t = threadIdx.x;
    if (t < BB*OO) d_bestkey[t] = 0ull;
    if (t < BB) d_numpos[t] = 0;
    if (t == 0) {
        a_lossl = 0.0; a_lossc = 0.0; a_lossp = 0.0; a_desk = 0.0; a_trips = 0.0;
        a_npp = 0ull; a_nnp = 0ull; a_tripc = 0ull;
    }
}

// Per-prior best truth + per-truth best prior (atomicMax on packed keys).
// grid (NCH, BB), 256 threads.
__global__ void k_match1(const float* __restrict__ dbox,
                         const float* __restrict__ tgt) {
    const int b = blockIdx.y;
    const int base = blockIdx.x * CH;
    const int tid = threadIdx.x;

    __shared__ float tx1[OO], ty1[OO], tx2[OO], ty2[OO], ta[OO];
    if (tid < OO) {
        const float* p = tgt + (size_t)(b*OO + tid)*9;
        tx1[tid] = p[0]; ty1[tid] = p[1]; tx2[tid] = p[2]; ty2[tid] = p[3];
        ta[tid]  = (p[2]-p[0])*(p[3]-p[1]);
    }
    __syncthreads();

    unsigned long long bk[OO];
#pragma unroll
    for (int t = 0; t < OO; t++) bk[t] = 0ull;

    int dend = base + CH; if (dend > DD) dend = DD;
    for (int d = base + tid; d < dend; d += 256) {
        float4 db = __ldg((const float4*)(dbox + d*4));
        float px1 = db.x - db.z*0.5f, py1 = db.y - db.w*0.5f;
        float px2 = db.x + db.z*0.5f, py2 = db.y + db.w*0.5f;
        float pa = (px2-px1)*(py2-py1);
        float mv = -1.0f; int mt = 0;
#pragma unroll
        for (int t = 0; t < OO; t++) {
            float ix = fmaxf(fminf(tx2[t], px2) - fmaxf(tx1[t], px1), 0.0f);
            float iy = fmaxf(fminf(ty2[t], py2) - fmaxf(ty1[t], py1), 0.0f);
            float inter = ix * iy;
            float iou = inter / (ta[t] + pa - inter);
            if (iou > mv) { mv = iou; mt = t; }     // first occurrence over t
            unsigned long long key =
                ((unsigned long long)__float_as_uint(iou) << 32) |
                (unsigned long long)(0xFFFFFFFFu - (unsigned)d);
            if (key > bk[t]) bk[t] = key;           // max iou, tie -> min d
        }
        d_prov[b*DD + d] = mv;
        d_pidx[b*DD + d] = mt;
    }

    // warp-reduce keys, one atomic per warp per truth
#pragma unroll
    for (int t = 0; t < OO; t++) {
        unsigned long long k = bk[t];
#pragma unroll
        for (int s = 16; s > 0; s >>= 1) {
            unsigned long long o = __shfl_down_sync(0xffffffffu, k, s);
            if (o > k) k = o;
        }
        if ((tid & 31) == 0 && k)
            atomicMax(&d_bestkey[b*OO + t], k);
    }
}

// Apply best-prior overrides (sequential in t per batch, last-wins).
__global__ void k_override() {
    int b = threadIdx.x;
    if (b < BB) {
        for (int t = 0; t < OO; t++) {
            unsigned long long k = d_bestkey[b*OO + t];
            int d = (int)(0xFFFFFFFFu - (unsigned)(k & 0xFFFFFFFFull));
            if (d >= 0 && d < DD) {
                d_prov[b*DD + d] = 2.0f;
                d_pidx[b*DD + d] = t;
            }
        }
    }
}

// conf_t + encode + loc/pose losses. grid (35, BB), 256 threads.
__global__ void k_enc(const float* __restrict__ loc,
                      const float* __restrict__ pose,
                      const float* __restrict__ dbox,
                      const float* __restrict__ tgt) {
    const int b = blockIdx.y;
    const int tid = threadIdx.x;
    const int d = blockIdx.x * 256 + tid;

    __shared__ float tx1[OO], ty1[OO], tx2[OO], ty2[OO];
    __shared__ float tpz[OO][3];
    __shared__ int   tlab[OO];
    if (tid < OO) {
        const float* p = tgt + (size_t)(b*OO + tid)*9;
        tx1[tid] = p[0]; ty1[tid] = p[1]; tx2[tid] = p[2]; ty2[tid] = p[3];
        tlab[tid] = (int)p[4];
        tpz[tid][0] = p[5]; tpz[tid][1] = p[6]; tpz[tid][2] = p[7];
    }
    __syncthreads();

    float ll = 0.0f, lp = 0.0f; int np = 0;
    if (d < DD) {
        int idx = b*DD + d;
        int t = d_pidx[idx];
        float ov = d_prov[idx];
        int cf = (ov < 0.5f) ? 0 : (tlab[t] + 1);
        d_conf[idx] = cf;
        if (cf > 0) {
            np = 1;
            float4 db = __ldg((const float4*)(dbox + d*4));
            float g0 = ((tx1[t] + tx2[t])*0.5f - db.x) / (0.1f * db.z);
            float g1 = ((ty1[t] + ty2[t])*0.5f - db.y) / (0.1f * db.w);
            float g2 = logf((tx2[t] - tx1[t]) / db.z) / 0.2f;
            float g3 = logf((ty2[t] - ty1[t]) / db.w) / 0.2f;
            float g[4] = {g0, g1, g2, g3};
#pragma unroll
            for (int i = 0; i < 4; i++) {
                float dd_ = loc[(size_t)idx*4 + i] - g[i];
                float ad = fabsf(dd_);
                ll += (ad < 1.0f) ? (0.5f*dd_*dd_) : (ad - 0.5f);
            }
#pragma unroll
            for (int i = 0; i < 3; i++) {
                float e = pose[(size_t)idx*3 + i] - tpz[t][i];
                lp += e*e;
            }
        }
    }

    __shared__ double sll[256], slp[256];
    __shared__ int    snp[256];
    sll[tid] = (double)ll; slp[tid] = (double)lp; snp[tid] = np;
    __syncthreads();
    for (int s = 128; s > 0; s >>= 1) {
        if (tid < s) { sll[tid] += sll[tid+s]; slp[tid] += slp[tid+s]; snp[tid] += snp[tid+s]; }
        __syncthreads();
    }
    if (tid == 0) {
        if (snp[0]) atomicAdd(&d_numpos[b], snp[0]);
        if (sll[0] != 0.0) atomicAdd(&a_lossl, sll[0]);
        if (slp[0] != 0.0) atomicAdd(&a_lossp, slp[0]);
    }
}

// CE per prior (poly exp on FMA pipe). Positives summed, negatives stored.
__global__ void k_ce(const float* __restrict__ conf) {
    int b = blockIdx.y;
    int d = blockIdx.x * blockDim.x + threadIdx.x;
    double pce = 0.0;
    if (d < DD) {
        int idx = b*DD + d;
        const float* x = conf + (size_t)idx * CC;
        float v[CC];
#pragma unroll
        for (int c = 0; c < CC; c++) v[c] = x[c];
        float m = v[0];
#pragma unroll
        for (int c = 1; c < CC; c++) m = fmaxf(m, v[c]);
        float s = 0.0f;
#pragma unroll
        for (int c = 0; c < CC; c++) s += fexp(v[c] - m);
        float lse = m + logf(s);
        int ct = d_conf[idx];
        float ce = lse - v[ct];
        if (ct > 0) { d_ceneg[idx] = 0.0f; pce = (double)ce; }
        else        { d_ceneg[idx] = ce; }
    }
    __shared__ double sp[256];
    sp[threadIdx.x] = pce;
    __syncthreads();
    for (int s = 128; s > 0; s >>= 1) {
        if (threadIdx.x < s) sp[threadIdx.x] += sp[threadIdx.x + s];
        __syncthreads();
    }
    if (threadIdx.x == 0 && sp[0] != 0.0) atomicAdd(&a_lossc, sp[0]);
}

// Exact top-k sum via smem-resident 4-pass byte radix select.
__global__ void k_topk() {
    const int b = blockIdx.x, tid = threadIdx.x;
    const int T = 256;
    __shared__ float sce[DD];
    __shared__ unsigned hist[256];
    __shared__ unsigned s_prefix;
    __shared__ int s_rem;

    int k = d_numpos[b] * 3;
    if (k > DD) k = DD;
    if (k <= 0) return;

    const float* ce = d_ceneg + (size_t)b * DD;
    for (int d = tid; d < DD; d += T) sce[d] = ce[d];
    if (tid == 0) { s_prefix = 0u; s_rem = k; }
    __syncthreads();

#pragma unroll
    for (int pass = 3; pass >= 0; pass--) {
        hist[tid] = 0u;
        __syncthreads();
        unsigned pref = s_prefix;
        int sh = pass * 8;
        for (int d = tid; d < DD; d += T) {
            unsigned u = __float_as_uint(sce[d]);
            bool ok = (pass == 3) || ((u >> (sh + 8)) == (pref >> (sh + 8)));
            if (ok) atomicAdd(&hist[(u >> sh) & 0xFFu], 1u);
        }
        __syncthreads();
        if (tid == 0) {
            int rem = s_rem; unsigned cum = 0u; int dg = 0;
            for (int g = 255; g >= 0; g--) {
                unsigned c = hist[g];
                if (cum + c >= (unsigned)rem) { dg = g; break; }
                cum += c;
            }
            s_prefix = pref | ((unsigned)dg << sh);
            s_rem = rem - (int)cum;
        }
        __syncthreads();
    }

    unsigned uT = s_prefix;
    float Tv = __uint_as_float(uT);
    double sg = 0.0; int cg = 0;
    for (int d = tid; d < DD; d += T) {
        float v = sce[d];
        if (__float_as_uint(v) > uT) { sg += (double)v; cg++; }
    }
    __shared__ double sdb[256];
    __shared__ int scn[256];
    sdb[tid] = sg; scn[tid] = cg;
    __syncthreads();
    for (int s = 128; s > 0; s >>= 1) {
        if (tid < s) { sdb[tid] += sdb[tid+s]; scn[tid] += scn[tid+s]; }
        __syncthreads();
    }
    if (tid == 0) {
        double contrib = sdb[0] + (double)(k - scn[0]) * (double)Tv;
        atomicAdd(&a_lossc, contrib);
    }
}

// Ordered compaction: positives in flat order, then earliest batch-0 negatives.
__global__ void k_compact(const float* __restrict__ line,
                          const float* __restrict__ tgt) {
    const int b = blockIdx.x, tid = threadIdx.x;
    const int CHP = (DD + 255) / 256; // 35
    int d0 = tid * CHP;
    int d1 = d0 + CHP; if (d1 > DD) d1 = DD;

    __shared__ int s_off, s_tot;
    if (tid == 0) {
        int acc = 0, off = 0;
        for (int i = 0; i < BB; i++) { if (i == b) off = acc; acc += d_numpos[i]; }
        s_off = off; s_tot = acc;
    }

    int cnt = 0;
    for (int d = d0; d < d1; d++) if (d_conf[b*DD + d] > 0) cnt++;
    __shared__ int sc[256];
    sc[tid] = cnt;
    __syncthreads();
    if (tid == 0) {
        int acc = 0;
        for (int i = 0; i < 256; i++) { int c = sc[i]; sc[i] = acc; acc += c; }
    }
    __syncthreads();

    int rank = s_off + sc[tid];
    for (int d = d0; d < d1 && rank < KK; d++) {
        int idx = b*DD + d;
        if (d_conf[idx] > 0) {
            int slot = rank++;
            d_lab[slot] = d_conf[idx];
            d_val[slot] = 1;
#pragma unroll
            for (int l = 0; l < LL; l++) d_emb[slot*LL + l] = line[(size_t)idx*LL + l];
            int t = d_pidx[idx];
            const float* p = tgt + (size_t)(b*OO + t)*9;
            d_qp[slot*3+0] = p[5]; d_qp[slot*3+1] = p[6]; d_qp[slot*3+2] = p[7];
        }
    }

    if (b == 0) {
        __syncthreads();
        __shared__ int smap[256];
        if (tid == 0) {
            int Pt = s_tot;
            int nr = 0;
            for (int d = 0; d < 256; d++) {
                int slot = -1;
                if (d_conf[d] == 0) {
                    int s2 = Pt + nr; nr++;
                    if (s2 < KK) slot = s2;
                }
                smap[d] = slot;
            }
        }
        __syncthreads();
        int d = tid;
        int slot = smap[d];
        if (slot >= 0) {
            d_lab[slot] = d_conf[d];
            d_val[slot] = 0;
#pragma unroll
            for (int l = 0; l < LL; l++) d_emb[slot*LL + l] = line[(size_t)d*LL + l];
            int t = d_pidx[d];
            const float* p = tgt + (size_t)t*9;
            d_qp[slot*3+0] = p[5]; d_qp[slot*3+1] = p[6]; d_qp[slot*3+2] = p[7];
        }
    }
}

// Pairwise distances, masks, desk sum, pair counts. Block i, thread j.
__global__ void k_pairs() {
    int i = blockIdx.x, j = threadIdx.x;
    __shared__ float ei[LL], ni[LL], qi[3];
    __shared__ int labi, vali;
    if (j < LL) ei[j] = d_emb[i*LL + j];
    if (j == 0) {
        labi = d_lab[i]; vali = d_val[i];
        qi[0] = d_qp[i*3+0]; qi[1] = d_qp[i*3+1]; qi[2] = d_qp[i*3+2];
    }
    __syncthreads();
    if (j == 0) {
        float s = 0.0f;
        for (int l = 0; l < LL; l++) s += ei[l]*ei[l];
        float n = fmaxf(sqrtf(s), 1e-12f);
        for (int l = 0; l < LL; l++) ni[l] = ei[l] / n;
    }
    __syncthreads();

    float ej[LL];
#pragma unroll
    for (int l = 0; l < LL; l++) ej[l] = d_emb[j*LL + l];
    float s = 0.0f;
#pragma unroll
    for (int l = 0; l < LL; l++) s += ej[l]*ej[l];
    float nj = fmaxf(sqrtf(s), 1e-12f);

    float sq = 0.0f, esq = 0.0f;
#pragma unroll
    for (int l = 0; l < LL; l++) {
        float dn = ni[l] - ej[l]/nj; sq  += dn*dn;
        float de = ei[l] - ej[l];    esq += de*de;
    }
    float dist = sqrtf(fmaxf(sq, 1e-12f));
    d_dist[i*KK + j] = dist;

    float qsq = 0.0f;
#pragma unroll
    for (int c = 0; c < 3; c++) { float dq = qi[c] - d_qp[j*3+c]; qsq += dq*dq; }

    bool vp   = vali && d_val[j] && (i != j);
    bool same = (labi == d_lab[j]);
    bool pp = vp &&  same && (dist > 0.2f);
    bool np = vp && !same && (dist < 0.8f);

    unsigned pb = __ballot_sync(0xffffffffu, pp);
    unsigned nb = __ballot_sync(0xffffffffu, np);
    if ((j & 31) == 0) { d_pm[i*8 + (j>>5)] = pb; d_nm[i*8 + (j>>5)] = nb; }

    double dk = pp ? (double)((esq - qsq) * (esq - qsq)) : 0.0;
    __shared__ double sdk[256];
    __shared__ int spp[256], snn[256];
    sdk[j] = dk; spp[j] = pp ? 1 : 0; snn[j] = np ? 1 : 0;
    __syncthreads();
    for (int st = 128; st > 0; st >>= 1) {
        if (j < st) { sdk[j] += sdk[j+st]; spp[j] += spp[j+st]; snn[j] += snn[j+st]; }
        __syncthreads();
    }
    if (j == 0) {
        if (sdk[0] != 0.0) atomicAdd(&a_desk, sdk[0]);
        if (spp[0]) atomicAdd(&a_npp, (unsigned long long)spp[0]);
        if (snn[0]) atomicAdd(&a_nnp, (unsigned long long)snn[0]);
    }
}

// Triplet loss: block i (anchor), thread = negative partner, loop positives.
__global__ void k_trip() {
    int i = blockIdx.x, tid = threadIdx.x;
    __shared__ float sdist[KK];
    __shared__ unsigned pm[8], nm[8];
    sdist[tid] = d_dist[i*KK + tid];
    if (tid < 8) { pm[tid] = d_pm[i*8 + tid]; nm[tid] = d_nm[i*8 + tid]; }
    __syncthreads();

    __shared__ int pj[KK];
    __shared__ int npj;
    if (tid == 0) {
        int n = 0;
        for (int w = 0; w < 8; w++) {
            unsigned m = pm[w];
            while (m) { int bpos = __ffs(m) - 1; pj[n++] = w*32 + bpos; m &= (m - 1); }
        }
        npj = n;
    }
    __syncthreads();
    int n = npj;
    if (n == 0) return;

    bool isneg = (nm[tid >> 5] >> (tid & 31)) & 1u;
    double ls = 0.0;
    unsigned long long lc = 0ull;
    if (isneg) {
        float dk = sdist[tid];
        for (int a = 0; a < n; a++) {
            float l = sdist[pj[a]] - dk + 0.2f;
            if (l > 0.0f) { ls += (double)l; lc++; }
        }
    }
    __shared__ double rs[256];
    __shared__ unsigned long long rc[256];
    rs[tid] = ls; rc[tid] = lc;
    __syncthreads();
    for (int s = 128; s > 0; s >>= 1) {
        if (tid < s) { rs[tid] += rs[tid+s]; rc[tid] += rc[tid+s]; }
        __syncthreads();
    }
    if (tid == 0 && (rs[0] != 0.0 || rc[0] != 0ull)) {
        atomicAdd(&a_trips, rs[0]);
        atomicAdd(&a_tripc, rc[0]);
    }
}

__global__ void k_final(float* __restrict__ out) {
    if (threadIdx.x == 0 && blockIdx.x == 0) {
        double N = 0.0;
        for (int b = 0; b < BB; b++) N += (double)d_numpos[b];
        if (N < 1.0) N = 1.0;
        double lossl = a_lossl / N;
        double lossc = a_lossc / N;
        double lossp = a_lossp / N;

        unsigned long long npp = a_npp;
        double dnpp = (npp < 1ull) ? 1.0 : (double)npp;
        unsigned long long tc = a_tripc;
        double losst = a_trips / (double)((tc < 1ull) ? 1ull : tc);
        unsigned long long pn = a_npp + a_nnp;
        double dpn = (pn < 1ull) ? 1.0 : (double)pn;

        double ldesk = a_desk / dnpp + losst / dpn;
        ldesk = ldesk / dnpp / 32.0;

        out[0] = (float)lossl;
        out[1] = (float)lossc;
        out[2] = (float)lossp;
        out[3] = (float)ldesk;
        out[4] = (float)losst;
    }
}

// ---------------- host launcher ----------------
extern "C" void kernel_launch(void* const* d_in, const int* in_sizes, int n_in,
                              void* d_out, int out_size) {
    const float *loc = 0, *conf = 0, *line = 0, *pose = 0, *dbox = 0, *tgt = 0;
    for (int i = 0; i < n_in; i++) {
        switch (in_sizes[i]) {
            case BB*DD*4:  loc  = (const float*)d_in[i]; break;
            case BB*DD*CC: conf = (const float*)d_in[i]; break;
            case BB*DD*LL: line = (const float*)d_in[i]; break;
            case BB*DD*3:  pose = (const float*)d_in[i]; break;
            case DD*4:     dbox = (const float*)d_in[i]; break;
            case BB*OO*9:  tgt  = (const float*)d_in[i]; break;
            default: break;
        }
    }
    if (!loc)  loc  = (const float*)d_in[0];
    if (!conf) conf = (const float*)d_in[1];
    if (!line) line = (const float*)d_in[2];
    if (!pose) pose = (const float*)d_in[3];
    if (!dbox) dbox = (const float*)d_in[4];
    if (!tgt)  tgt  = (const float*)d_in[5];

    k_init<<<1, 256>>>();
    k_match1<<<dim3(NCH, BB), 256>>>(dbox, tgt);
    k_override<<<1, 32>>>();
    k_enc<<<dim3((DD + 255) / 256, BB), 256>>>(loc, pose, dbox, tgt);
    k_ce<<<dim3((DD + 255) / 256, BB), 256>>>(conf);
    k_topk<<<BB, 256>>>();
    k_compact<<<BB, 256>>>(line, tgt);
    k_pairs<<<KK, 256>>>();
    k_trip<<<KK, 256>>>();
    k_final<<<1, 1>>>((float*)d_out);
}

// round 3
// speedup vs baseline: 1.9933x; 1.0150x over previous
#include <cuda_runtime.h>
#include <cuda_bf16.h>
#include <math.h>

#define BB 32
#define DD 8732
#define OO 8
#define CC 21
#define LL 32
#define KK 256
#define NCH 8
#define CH  1092   // NCH*CH = 8736 >= DD

// ---------------- device scratch ----------------
__device__ unsigned char d_ct[BB*DD];      // conf (5 bits) | truth idx (3 bits)
__device__ float  d_ceneg[BB*DD];
__device__ int    d_numpos[BB];
__device__ unsigned long long d_bestkey[BB*OO];

__device__ double a_lossl, a_lossc, a_lossp, a_desk, a_trips;
__device__ unsigned long long a_npp, a_nnp, a_tripc;

__device__ float  d_emb[KK*LL];
__device__ int    d_lab[KK];
__device__ float  d_qp[KK*3];
__device__ int    d_val[KK];

// fast exp on the FMA pipe (inputs are x - max <= 0)
__device__ __forceinline__ float fexp(float x) {
    x = fmaxf(x, -80.0f);
    float y = x * 1.442695040888963f;
    float n = rintf(y);
    float f = y - n;                       // [-0.5, 0.5]
    float p = 1.54035303933816e-4f;
    p = fmaf(p, f, 1.33335581464284e-3f);
    p = fmaf(p, f, 9.61812910762848e-3f);
    p = fmaf(p, f, 5.55041086648216e-2f);
    p = fmaf(p, f, 2.40226506959101e-1f);
    p = fmaf(p, f, 6.93147180559945e-1f);
    p = fmaf(p, f, 1.0f);
    return __int_as_float(__float_as_int(p) + (((int)n) << 23));
}

// ---------------- kernels ----------------
__global__ void k_init() {
    int t = threadIdx.x;
    if (t < BB*OO) d_bestkey[t] = 0ull;
    if (t < BB) d_numpos[t] = 0;
    if (t == 0) {
        a_lossl = 0.0; a_lossc = 0.0; a_lossp = 0.0; a_desk = 0.0; a_trips = 0.0;
        a_npp = 0ull; a_nnp = 0ull; a_tripc = 0ull;
    }
}

// Per-truth best prior only (atomicMax on packed (iou, ~d) keys).
__global__ void k_match1(const float* __restrict__ dbox,
                         const float* __restrict__ tgt) {
    const int b = blockIdx.y;
    const int base = blockIdx.x * CH;
    const int tid = threadIdx.x;

    __shared__ float tx1[OO], ty1[OO], tx2[OO], ty2[OO], ta[OO];
    if (tid < OO) {
        const float* p = tgt + (size_t)(b*OO + tid)*9;
        tx1[tid] = p[0]; ty1[tid] = p[1]; tx2[tid] = p[2]; ty2[tid] = p[3];
        ta[tid]  = (p[2]-p[0])*(p[3]-p[1]);
    }
    __syncthreads();

    unsigned long long bk[OO];
#pragma unroll
    for (int t = 0; t < OO; t++) bk[t] = 0ull;

    int dend = base + CH; if (dend > DD) dend = DD;
    for (int d = base + tid; d < dend; d += 256) {
        float4 db = __ldg((const float4*)(dbox + d*4));
        float px1 = db.x - db.z*0.5f, py1 = db.y - db.w*0.5f;
        float px2 = db.x + db.z*0.5f, py2 = db.y + db.w*0.5f;
        float pa = (px2-px1)*(py2-py1);
#pragma unroll
        for (int t = 0; t < OO; t++) {
            float ix = fmaxf(fminf(tx2[t], px2) - fmaxf(tx1[t], px1), 0.0f);
            float iy = fmaxf(fminf(ty2[t], py2) - fmaxf(ty1[t], py1), 0.0f);
            float inter = ix * iy;
            float iou = inter / (ta[t] + pa - inter);
            unsigned long long key =
                ((unsigned long long)__float_as_uint(iou) << 32) |
                (unsigned long long)(0xFFFFFFFFu - (unsigned)d);
            if (key > bk[t]) bk[t] = key;
        }
    }

#pragma unroll
    for (int t = 0; t < OO; t++) {
        unsigned long long k = bk[t];
#pragma unroll
        for (int s = 16; s > 0; s >>= 1) {
            unsigned long long o = __shfl_down_sync(0xffffffffu, k, s);
            if (o > k) k = o;
        }
        if ((tid & 31) == 0 && k)
            atomicMax(&d_bestkey[b*OO + t], k);
    }
}

// Fused: recompute per-prior best truth, apply overrides, conf_t, encode,
// loc/pose losses, and CE (positives summed, negatives stored).
__global__ void k_encce(const float* __restrict__ loc,
                        const float* __restrict__ pose,
                        const float* __restrict__ dbox,
                        const float* __restrict__ tgt,
                        const float* __restrict__ conf) {
    const int b = blockIdx.y;
    const int tid = threadIdx.x;
    const int d = blockIdx.x * 256 + tid;

    __shared__ float tx1[OO], ty1[OO], tx2[OO], ty2[OO], ta[OO];
    __shared__ float tpz[OO][3];
    __shared__ int   tlab[OO], bestd[OO];
    if (tid < OO) {
        const float* p = tgt + (size_t)(b*OO + tid)*9;
        tx1[tid] = p[0]; ty1[tid] = p[1]; tx2[tid] = p[2]; ty2[tid] = p[3];
        ta[tid]  = (p[2]-p[0])*(p[3]-p[1]);
        tlab[tid] = (int)p[4];
        tpz[tid][0] = p[5]; tpz[tid][1] = p[6]; tpz[tid][2] = p[7];
        unsigned long long k = d_bestkey[b*OO + tid];
        bestd[tid] = (int)(0xFFFFFFFFu - (unsigned)(k & 0xFFFFFFFFull));
    }
    __syncthreads();

    float ll = 0.0f, lp = 0.0f, cepos = 0.0f;
    int np = 0;
    if (d < DD) {
        int idx = b*DD + d;
        float4 db = __ldg((const float4*)(dbox + d*4));
        float px1 = db.x - db.z*0.5f, py1 = db.y - db.w*0.5f;
        float px2 = db.x + db.z*0.5f, py2 = db.y + db.w*0.5f;
        float pa = (px2-px1)*(py2-py1);
        float mv = -1.0f; int mt = 0;
#pragma unroll
        for (int t = 0; t < OO; t++) {
            float ix = fmaxf(fminf(tx2[t], px2) - fmaxf(tx1[t], px1), 0.0f);
            float iy = fmaxf(fminf(ty2[t], py2) - fmaxf(ty1[t], py1), 0.0f);
            float inter = ix * iy;
            float iou = inter / (ta[t] + pa - inter);
            if (iou > mv) { mv = iou; mt = t; }   // first occurrence over t
        }
#pragma unroll
        for (int t = 0; t < OO; t++) {            // overrides, last t wins
            if (bestd[t] == d) { mv = 2.0f; mt = t; }
        }
        int cf = (mv < 0.5f) ? 0 : (tlab[mt] + 1);
        d_ct[idx] = (unsigned char)(cf | (mt << 5));

        if (cf > 0) {
            np = 1;
            float g0 = ((tx1[mt] + tx2[mt])*0.5f - db.x) / (0.1f * db.z);
            float g1 = ((ty1[mt] + ty2[mt])*0.5f - db.y) / (0.1f * db.w);
            float g2 = logf((tx2[mt] - tx1[mt]) / db.z) / 0.2f;
            float g3 = logf((ty2[mt] - ty1[mt]) / db.w) / 0.2f;
            float g[4] = {g0, g1, g2, g3};
#pragma unroll
            for (int i = 0; i < 4; i++) {
                float dd_ = loc[(size_t)idx*4 + i] - g[i];
                float ad = fabsf(dd_);
                ll += (ad < 1.0f) ? (0.5f*dd_*dd_) : (ad - 0.5f);
            }
#pragma unroll
            for (int i = 0; i < 3; i++) {
                float e = pose[(size_t)idx*3 + i] - tpz[mt][i];
                lp += e*e;
            }
        }

        // CE
        const float* x = conf + (size_t)idx * CC;
        float v[CC];
#pragma unroll
        for (int c = 0; c < CC; c++) v[c] = __ldg(x + c);
        float m = v[0];
#pragma unroll
        for (int c = 1; c < CC; c++) m = fmaxf(m, v[c]);
        float s = 0.0f;
#pragma unroll
        for (int c = 0; c < CC; c++) s += fexp(v[c] - m);
        float lse = m + logf(s);
        float ce = lse - v[cf];
        if (cf > 0) { d_ceneg[idx] = 0.0f; cepos = ce; }
        else        { d_ceneg[idx] = ce; }
    }

    // block reduce: ll, lp, cepos (doubles), np (int)
    double rll = (double)ll, rlp = (double)lp, rce = (double)cepos;
    int rnp = np;
#pragma unroll
    for (int s = 16; s > 0; s >>= 1) {
        rll += __shfl_down_sync(0xffffffffu, rll, s);
        rlp += __shfl_down_sync(0xffffffffu, rlp, s);
        rce += __shfl_down_sync(0xffffffffu, rce, s);
        rnp += __shfl_down_sync(0xffffffffu, rnp, s);
    }
    __shared__ double wll[8], wlp[8], wce[8];
    __shared__ int wnp[8];
    int wid = tid >> 5, lane = tid & 31;
    if (lane == 0) { wll[wid] = rll; wlp[wid] = rlp; wce[wid] = rce; wnp[wid] = rnp; }
    __syncthreads();
    if (wid == 0) {
        rll = (lane < 8) ? wll[lane] : 0.0;
        rlp = (lane < 8) ? wlp[lane] : 0.0;
        rce = (lane < 8) ? wce[lane] : 0.0;
        rnp = (lane < 8) ? wnp[lane] : 0;
#pragma unroll
        for (int s = 4; s > 0; s >>= 1) {
            rll += __shfl_down_sync(0xffu, rll, s);
            rlp += __shfl_down_sync(0xffu, rlp, s);
            rce += __shfl_down_sync(0xffu, rce, s);
            rnp += __shfl_down_sync(0xffu, rnp, s);
        }
        if (lane == 0) {
            if (rnp) atomicAdd(&d_numpos[b], rnp);
            if (rll != 0.0) atomicAdd(&a_lossl, rll);
            if (rlp != 0.0) atomicAdd(&a_lossp, rlp);
            if (rce != 0.0) atomicAdd(&a_lossc, rce);
        }
    }
}

// Exact top-k sum via smem-resident 4-pass byte radix select.
__global__ void k_topk() {
    const int b = blockIdx.x, tid = threadIdx.x;
    const int T = 256;
    __shared__ float sce[DD];
    __shared__ unsigned hist[256];
    __shared__ unsigned s_prefix;
    __shared__ int s_rem;

    int k = d_numpos[b] * 3;
    if (k > DD) k = DD;
    if (k <= 0) return;

    const float* ce = d_ceneg + (size_t)b * DD;
    for (int d = tid; d < DD; d += T) sce[d] = ce[d];
    if (tid == 0) { s_prefix = 0u; s_rem = k; }
    __syncthreads();

#pragma unroll
    for (int pass = 3; pass >= 0; pass--) {
        hist[tid] = 0u;
        __syncthreads();
        unsigned pref = s_prefix;
        int sh = pass * 8;
        for (int d = tid; d < DD; d += T) {
            unsigned u = __float_as_uint(sce[d]);
            bool ok = (pass == 3) || ((u >> (sh + 8)) == (pref >> (sh + 8)));
            if (ok) atomicAdd(&hist[(u >> sh) & 0xFFu], 1u);
        }
        __syncthreads();
        if (tid == 0) {
            int rem = s_rem; unsigned cum = 0u; int dg = 0;
            for (int g = 255; g >= 0; g--) {
                unsigned c = hist[g];
                if (cum + c >= (unsigned)rem) { dg = g; break; }
                cum += c;
            }
            s_prefix = pref | ((unsigned)dg << sh);
            s_rem = rem - (int)cum;
        }
        __syncthreads();
    }

    unsigned uT = s_prefix;
    float Tv = __uint_as_float(uT);
    double sg = 0.0; int cg = 0;
    for (int d = tid; d < DD; d += T) {
        float v = sce[d];
        if (__float_as_uint(v) > uT) { sg += (double)v; cg++; }
    }
#pragma unroll
    for (int s = 16; s > 0; s >>= 1) {
        sg += __shfl_down_sync(0xffffffffu, sg, s);
        cg += __shfl_down_sync(0xffffffffu, cg, s);
    }
    __shared__ double wsg[8];
    __shared__ int wcg[8];
    int wid = tid >> 5, lane = tid & 31;
    if (lane == 0) { wsg[wid] = sg; wcg[wid] = cg; }
    __syncthreads();
    if (tid == 0) {
        double tsg = 0.0; int tcg = 0;
        for (int i = 0; i < 8; i++) { tsg += wsg[i]; tcg += wcg[i]; }
        atomicAdd(&a_lossc, tsg + (double)(k - tcg) * (double)Tv);
    }
}

// Ordered compaction: positives in flat order, then earliest batch-0 negatives.
__global__ void k_compact(const float* __restrict__ line,
                          const float* __restrict__ tgt) {
    const int b = blockIdx.x, tid = threadIdx.x;
    const int CHP = (DD + 255) / 256; // 35
    int d0 = tid * CHP;
    int d1 = d0 + CHP; if (d1 > DD) d1 = DD;

    __shared__ int s_off, s_tot;
    if (tid == 0) {
        int acc = 0, off = 0;
        for (int i = 0; i < BB; i++) { if (i == b) off = acc; acc += d_numpos[i]; }
        s_off = off; s_tot = acc;
    }

    int cnt = 0;
    for (int d = d0; d < d1; d++) if ((d_ct[b*DD + d] & 31) > 0) cnt++;
    __shared__ int sc[256];
    sc[tid] = cnt;
    __syncthreads();
    if (tid == 0) {
        int acc = 0;
        for (int i = 0; i < 256; i++) { int c = sc[i]; sc[i] = acc; acc += c; }
    }
    __syncthreads();

    int rank = s_off + sc[tid];
    for (int d = d0; d < d1 && rank < KK; d++) {
        int idx = b*DD + d;
        unsigned char ct = d_ct[idx];
        int cf = ct & 31;
        if (cf > 0) {
            int slot = rank++;
            d_lab[slot] = cf;
            d_val[slot] = 1;
#pragma unroll
            for (int l = 0; l < LL; l++) d_emb[slot*LL + l] = line[(size_t)idx*LL + l];
            int t = ct >> 5;
            const float* p = tgt + (size_t)(b*OO + t)*9;
            d_qp[slot*3+0] = p[5]; d_qp[slot*3+1] = p[6]; d_qp[slot*3+2] = p[7];
        }
    }

    if (b == 0) {
        __syncthreads();
        __shared__ int smap[256];
        if (tid == 0) {
            int Pt = s_tot;
            int nr = 0;
            for (int d = 0; d < 256; d++) {
                int slot = -1;
                if ((d_ct[d] & 31) == 0) {
                    int s2 = Pt + nr; nr++;
                    if (s2 < KK) slot = s2;
                }
                smap[d] = slot;
            }
        }
        __syncthreads();
        int d = tid;
        int slot = smap[d];
        if (slot >= 0) {
            unsigned char ct = d_ct[d];
            d_lab[slot] = ct & 31;
            d_val[slot] = 0;
#pragma unroll
            for (int l = 0; l < LL; l++) d_emb[slot*LL + l] = line[(size_t)d*LL + l];
            int t = ct >> 5;
            const float* p = tgt + (size_t)t*9;
            d_qp[slot*3+0] = p[5]; d_qp[slot*3+1] = p[6]; d_qp[slot*3+2] = p[7];
        }
    }
}

// Fused pairwise + triplet. Block i (anchor), thread j (partner).
__global__ void k_pairstrip() {
    int i = blockIdx.x, j = threadIdx.x;
    __shared__ float ei[LL], ni[LL], qi[3];
    __shared__ int labi, vali;
    __shared__ float sdist[KK];
    __shared__ unsigned pm[8], nm[8];

    if (j < LL) ei[j] = d_emb[i*LL + j];
    if (j == 0) {
        labi = d_lab[i]; vali = d_val[i];
        qi[0] = d_qp[i*3+0]; qi[1] = d_qp[i*3+1]; qi[2] = d_qp[i*3+2];
    }
    __syncthreads();
    if (j == 0) {
        float s = 0.0f;
        for (int l = 0; l < LL; l++) s += ei[l]*ei[l];
        float n = fmaxf(sqrtf(s), 1e-12f);
        for (int l = 0; l < LL; l++) ni[l] = ei[l] / n;
    }
    __syncthreads();

    float ej[LL];
#pragma unroll
    for (int l = 0; l < LL; l++) ej[l] = d_emb[j*LL + l];
    float s = 0.0f;
#pragma unroll
    for (int l = 0; l < LL; l++) s += ej[l]*ej[l];
    float rnj = 1.0f / fmaxf(sqrtf(s), 1e-12f);

    float sq = 0.0f, esq = 0.0f;
#pragma unroll
    for (int l = 0; l < LL; l++) {
        float dn = ni[l] - ej[l]*rnj; sq  += dn*dn;
        float de = ei[l] - ej[l];     esq += de*de;
    }
    float dist = sqrtf(fmaxf(sq, 1e-12f));
    sdist[j] = dist;

    float qsq = 0.0f;
#pragma unroll
    for (int c = 0; c < 3; c++) { float dq = qi[c] - d_qp[j*3+c]; qsq += dq*dq; }

    bool vp   = vali && d_val[j] && (i != j);
    bool same = (labi == d_lab[j]);
    bool pp = vp &&  same && (dist > 0.2f);
    bool np = vp && !same && (dist < 0.8f);

    unsigned pb = __ballot_sync(0xffffffffu, pp);
    unsigned nb = __ballot_sync(0xffffffffu, np);
    if ((j & 31) == 0) { pm[j>>5] = pb; nm[j>>5] = nb; }

    // reduce desk + counts
    double dk = pp ? (double)((esq - qsq) * (esq - qsq)) : 0.0;
    int cp = pp ? 1 : 0, cn = np ? 1 : 0;
#pragma unroll
    for (int st = 16; st > 0; st >>= 1) {
        dk += __shfl_down_sync(0xffffffffu, dk, st);
        cp += __shfl_down_sync(0xffffffffu, cp, st);
        cn += __shfl_down_sync(0xffffffffu, cn, st);
    }
    __shared__ double wdk[8];
    __shared__ int wcp[8], wcn[8];
    int wid = j >> 5, lane = j & 31;
    if (lane == 0) { wdk[wid] = dk; wcp[wid] = cp; wcn[wid] = cn; }
    __syncthreads();
    if (j == 0) {
        double t = 0.0; int p = 0, n = 0;
        for (int w = 0; w < 8; w++) { t += wdk[w]; p += wcp[w]; n += wcn[w]; }
        if (t != 0.0) atomicAdd(&a_desk, t);
        if (p) atomicAdd(&a_npp, (unsigned long long)p);
        if (n) atomicAdd(&a_nnp, (unsigned long long)n);
    }

    // triplet: thread j = negative partner, loop positive list
    __shared__ int pj[KK];
    __shared__ int npj;
    if (j == 0) {
        int n = 0;
        for (int w = 0; w < 8; w++) {
            unsigned m = pm[w];
            while (m) { int bp = __ffs(m) - 1; pj[n++] = w*32 + bp; m &= (m - 1); }
        }
        npj = n;
    }
    __syncthreads();
    int n = npj;
    if (n == 0) return;

    bool isneg = (nm[j >> 5] >> (j & 31)) & 1u;
    double ls = 0.0;
    int lc = 0;
    if (isneg) {
        float dk2 = sdist[j];
        for (int a = 0; a < n; a++) {
            float l = sdist[pj[a]] - dk2 + 0.2f;
            if (l > 0.0f) { ls += (double)l; lc++; }
        }
    }
#pragma unroll
    for (int st = 16; st > 0; st >>= 1) {
        ls += __shfl_down_sync(0xffffffffu, ls, st);
        lc += __shfl_down_sync(0xffffffffu, lc, st);
    }
    __shared__ double wls[8];
    __shared__ int wlc[8];
    if (lane == 0) { wls[wid] = ls; wlc[wid] = lc; }
    __syncthreads();
    if (j == 0) {
        double t = 0.0; unsigned long long c = 0ull;
        for (int w = 0; w < 8; w++) { t += wls[w]; c += (unsigned long long)wlc[w]; }
        if (t != 0.0 || c != 0ull) {
            atomicAdd(&a_trips, t);
            atomicAdd(&a_tripc, c);
        }
    }
}

__global__ void k_final(float* __restrict__ out) {
    if (threadIdx.x == 0 && blockIdx.x == 0) {
        double N = 0.0;
        for (int b = 0; b < BB; b++) N += (double)d_numpos[b];
        if (N < 1.0) N = 1.0;
        double lossl = a_lossl / N;
        double lossc = a_lossc / N;
        double lossp = a_lossp / N;

        unsigned long long npp = a_npp;
        double dnpp = (npp < 1ull) ? 1.0 : (double)npp;
        unsigned long long tc = a_tripc;
        double losst = a_trips / (double)((tc < 1ull) ? 1ull : tc);
        unsigned long long pn = a_npp + a_nnp;
        double dpn = (pn < 1ull) ? 1.0 : (double)pn;

        double ldesk = a_desk / dnpp + losst / dpn;
        ldesk = ldesk / dnpp / 32.0;

        out[0] = (float)lossl;
        out[1] = (float)lossc;
        out[2] = (float)lossp;
        out[3] = (float)ldesk;
        out[4] = (float)losst;
    }
}

// ---------------- host launcher ----------------
extern "C" void kernel_launch(void* const* d_in, const int* in_sizes, int n_in,
                              void* d_out, int out_size) {
    const float *loc = 0, *conf = 0, *line = 0, *pose = 0, *dbox = 0, *tgt = 0;
    for (int i = 0; i < n_in; i++) {
        switch (in_sizes[i]) {
            case BB*DD*4:  loc  = (const float*)d_in[i]; break;
            case BB*DD*CC: conf = (const float*)d_in[i]; break;
            case BB*DD*LL: line = (const float*)d_in[i]; break;
            case BB*DD*3:  pose = (const float*)d_in[i]; break;
            case DD*4:     dbox = (const float*)d_in[i]; break;
            case BB*OO*9:  tgt  = (const float*)d_in[i]; break;
            default: break;
        }
    }
    if (!loc)  loc  = (const float*)d_in[0];
    if (!conf) conf = (const float*)d_in[1];
    if (!line) line = (const float*)d_in[2];
    if (!pose) pose = (const float*)d_in[3];
    if (!dbox) dbox = (const float*)d_in[4];
    if (!tgt)  tgt  = (const float*)d_in[5];

    k_init<<<1, 256>>>();
    k_match1<<<dim3(NCH, BB), 256>>>(dbox, tgt);
    k_encce<<<dim3((DD + 255) / 256, BB), 256>>>(loc, pose, dbox, tgt, conf);
    k_topk<<<BB, 256>>>();
    k_compact<<<BB, 256>>>(line, tgt);
    k_pairstrip<<<KK, 256>>>();
    k_final<<<1, 1>>>((float*)d_out);
}

// round 4
// speedup vs baseline: 2.1858x; 1.0966x over previous
#include <cuda_runtime.h>
#include <cuda_bf16.h>
#include <math.h>

#define BB 32
#define DD 8732
#define OO 8
#define CC 21
#define LL 32
#define KK 256
#define NCH 8
#define CH  1092   // NCH*CH = 8736 >= DD

// ---------------- device scratch ----------------
__device__ unsigned char d_ct[BB*DD];      // conf (5 bits) | truth idx (3 bits)
__device__ float  d_ceneg[BB*DD];
__device__ int    d_numpos[BB];
__device__ unsigned long long d_bestkey[BB*OO];

__device__ double a_lossl, a_lossc, a_lossp, a_desk, a_trips;
__device__ unsigned long long a_npp, a_nnp, a_tripc;

__device__ float  d_emb[KK*LL];
__device__ int    d_lab[KK];
__device__ float  d_qp[KK*3];
__device__ int    d_val[KK];

// fast exp on the FMA pipe (inputs are x - max <= 0)
__device__ __forceinline__ float fexp(float x) {
    x = fmaxf(x, -80.0f);
    float y = x * 1.442695040888963f;
    float n = rintf(y);
    float f = y - n;                       // [-0.5, 0.5]
    float p = 1.54035303933816e-4f;
    p = fmaf(p, f, 1.33335581464284e-3f);
    p = fmaf(p, f, 9.61812910762848e-3f);
    p = fmaf(p, f, 5.55041086648216e-2f);
    p = fmaf(p, f, 2.40226506959101e-1f);
    p = fmaf(p, f, 6.93147180559945e-1f);
    p = fmaf(p, f, 1.0f);
    return __int_as_float(__float_as_int(p) + (((int)n) << 23));
}

// ---------------- kernels ----------------
__global__ void k_init() {
    int t = threadIdx.x;
    if (t < BB*OO) d_bestkey[t] = 0ull;
    if (t < BB) d_numpos[t] = 0;
    if (t == 0) {
        a_lossl = 0.0; a_lossc = 0.0; a_lossp = 0.0; a_desk = 0.0; a_trips = 0.0;
        a_npp = 0ull; a_nnp = 0ull; a_tripc = 0ull;
    }
}

// Per-truth best prior only (atomicMax on packed (iou, ~d) keys).
__global__ void k_match1(const float* __restrict__ dbox,
                         const float* __restrict__ tgt) {
    const int b = blockIdx.y;
    const int base = blockIdx.x * CH;
    const int tid = threadIdx.x;

    __shared__ float tx1[OO], ty1[OO], tx2[OO], ty2[OO], ta[OO];
    if (tid < OO) {
        const float* p = tgt + (size_t)(b*OO + tid)*9;
        tx1[tid] = p[0]; ty1[tid] = p[1]; tx2[tid] = p[2]; ty2[tid] = p[3];
        ta[tid]  = (p[2]-p[0])*(p[3]-p[1]);
    }
    __syncthreads();

    unsigned long long bk[OO];
#pragma unroll
    for (int t = 0; t < OO; t++) bk[t] = 0ull;

    int dend = base + CH; if (dend > DD) dend = DD;
    for (int d = base + tid; d < dend; d += 256) {
        float4 db = __ldg((const float4*)(dbox + d*4));
        float px1 = db.x - db.z*0.5f, py1 = db.y - db.w*0.5f;
        float px2 = db.x + db.z*0.5f, py2 = db.y + db.w*0.5f;
        float pa = (px2-px1)*(py2-py1);
#pragma unroll
        for (int t = 0; t < OO; t++) {
            float ix = fmaxf(fminf(tx2[t], px2) - fmaxf(tx1[t], px1), 0.0f);
            float iy = fmaxf(fminf(ty2[t], py2) - fmaxf(ty1[t], py1), 0.0f);
            float inter = ix * iy;
            float iou = inter / (ta[t] + pa - inter);
            unsigned long long key =
                ((unsigned long long)__float_as_uint(iou) << 32) |
                (unsigned long long)(0xFFFFFFFFu - (unsigned)d);
            if (key > bk[t]) bk[t] = key;
        }
    }

#pragma unroll
    for (int t = 0; t < OO; t++) {
        unsigned long long k = bk[t];
#pragma unroll
        for (int s = 16; s > 0; s >>= 1) {
            unsigned long long o = __shfl_down_sync(0xffffffffu, k, s);
            if (o > k) k = o;
        }
        if ((tid & 31) == 0 && k)
            atomicMax(&d_bestkey[b*OO + t], k);
    }
}

// Fused: recompute per-prior best truth, apply overrides, conf_t, encode,
// loc/pose losses, and CE (positives summed, negatives stored).
__global__ void k_encce(const float* __restrict__ loc,
                        const float* __restrict__ pose,
                        const float* __restrict__ dbox,
                        const float* __restrict__ tgt,
                        const float* __restrict__ conf) {
    const int b = blockIdx.y;
    const int tid = threadIdx.x;
    const int d = blockIdx.x * 256 + tid;

    __shared__ float tx1[OO], ty1[OO], tx2[OO], ty2[OO], ta[OO];
    __shared__ float tpz[OO][3];
    __shared__ int   tlab[OO], bestd[OO];
    __shared__ float sconf[256*CC];

    if (tid < OO) {
        const float* p = tgt + (size_t)(b*OO + tid)*9;
        tx1[tid] = p[0]; ty1[tid] = p[1]; tx2[tid] = p[2]; ty2[tid] = p[3];
        ta[tid]  = (p[2]-p[0])*(p[3]-p[1]);
        tlab[tid] = (int)p[4];
        tpz[tid][0] = p[5]; tpz[tid][1] = p[6]; tpz[tid][2] = p[7];
        unsigned long long k = d_bestkey[b*OO + tid];
        bestd[tid] = (int)(0xFFFFFFFFu - (unsigned)(k & 0xFFFFFFFFull));
    }
    // coalesced stage of this block's conf tile
    {
        int d0 = blockIdx.x * 256;
        int nblk = DD - d0; if (nblk > 256) nblk = 256;
        const float* cbase = conf + ((size_t)b*DD + d0)*CC;
        for (int i = tid; i < nblk*CC; i += 256) sconf[i] = cbase[i];
    }
    __syncthreads();

    float ll = 0.0f, lp = 0.0f, cepos = 0.0f;
    int np = 0;
    if (d < DD) {
        int idx = b*DD + d;
        float4 db = __ldg((const float4*)(dbox + d*4));
        float px1 = db.x - db.z*0.5f, py1 = db.y - db.w*0.5f;
        float px2 = db.x + db.z*0.5f, py2 = db.y + db.w*0.5f;
        float pa = (px2-px1)*(py2-py1);
        float mv = -1.0f; int mt = 0;
#pragma unroll
        for (int t = 0; t < OO; t++) {
            float ix = fmaxf(fminf(tx2[t], px2) - fmaxf(tx1[t], px1), 0.0f);
            float iy = fmaxf(fminf(ty2[t], py2) - fmaxf(ty1[t], py1), 0.0f);
            float inter = ix * iy;
            float iou = inter / (ta[t] + pa - inter);
            if (iou > mv) { mv = iou; mt = t; }   // first occurrence over t
        }
#pragma unroll
        for (int t = 0; t < OO; t++) {            // overrides, last t wins
            if (bestd[t] == d) { mv = 2.0f; mt = t; }
        }
        int cf = (mv < 0.5f) ? 0 : (tlab[mt] + 1);
        d_ct[idx] = (unsigned char)(cf | (mt << 5));

        if (cf > 0) {
            np = 1;
            float g0 = ((tx1[mt] + tx2[mt])*0.5f - db.x) / (0.1f * db.z);
            float g1 = ((ty1[mt] + ty2[mt])*0.5f - db.y) / (0.1f * db.w);
            float g2 = logf((tx2[mt] - tx1[mt]) / db.z) / 0.2f;
            float g3 = logf((ty2[mt] - ty1[mt]) / db.w) / 0.2f;
            float g[4] = {g0, g1, g2, g3};
#pragma unroll
            for (int i = 0; i < 4; i++) {
                float dd_ = loc[(size_t)idx*4 + i] - g[i];
                float ad = fabsf(dd_);
                ll += (ad < 1.0f) ? (0.5f*dd_*dd_) : (ad - 0.5f);
            }
#pragma unroll
            for (int i = 0; i < 3; i++) {
                float e = pose[(size_t)idx*3 + i] - tpz[mt][i];
                lp += e*e;
            }
        }

        // CE from smem tile (stride 21 -> bank-conflict free)
        const float* v = sconf + tid*CC;
        float m = v[0];
#pragma unroll
        for (int c = 1; c < CC; c++) m = fmaxf(m, v[c]);
        float s = 0.0f;
#pragma unroll
        for (int c = 0; c < CC; c++) s += fexp(v[c] - m);
        float lse = m + logf(s);
        float ce = lse - v[cf];
        if (cf > 0) { d_ceneg[idx] = 0.0f; cepos = ce; }
        else        { d_ceneg[idx] = ce; }
    }

    // block reduce
    double rll = (double)ll, rlp = (double)lp, rce = (double)cepos;
    int rnp = np;
#pragma unroll
    for (int s = 16; s > 0; s >>= 1) {
        rll += __shfl_down_sync(0xffffffffu, rll, s);
        rlp += __shfl_down_sync(0xffffffffu, rlp, s);
        rce += __shfl_down_sync(0xffffffffu, rce, s);
        rnp += __shfl_down_sync(0xffffffffu, rnp, s);
    }
    __shared__ double wll[8], wlp[8], wce[8];
    __shared__ int wnp[8];
    int wid = tid >> 5, lane = tid & 31;
    if (lane == 0) { wll[wid] = rll; wlp[wid] = rlp; wce[wid] = rce; wnp[wid] = rnp; }
    __syncthreads();
    if (wid == 0) {
        rll = (lane < 8) ? wll[lane] : 0.0;
        rlp = (lane < 8) ? wlp[lane] : 0.0;
        rce = (lane < 8) ? wce[lane] : 0.0;
        rnp = (lane < 8) ? wnp[lane] : 0;
#pragma unroll
        for (int s = 4; s > 0; s >>= 1) {
            rll += __shfl_down_sync(0xffu, rll, s);
            rlp += __shfl_down_sync(0xffu, rlp, s);
            rce += __shfl_down_sync(0xffu, rce, s);
            rnp += __shfl_down_sync(0xffu, rnp, s);
        }
        if (lane == 0) {
            if (rnp) atomicAdd(&d_numpos[b], rnp);
            if (rll != 0.0) atomicAdd(&a_lossl, rll);
            if (rlp != 0.0) atomicAdd(&a_lossp, rlp);
            if (rce != 0.0) atomicAdd(&a_lossc, rce);
        }
    }
}

// Exact top-k sum via smem-resident 4-pass byte radix select.
// 1024 threads; warp-aggregated histogram atomics; warp suffix-scan select.
__global__ void __launch_bounds__(1024) k_topk() {
    const int b = blockIdx.x, tid = threadIdx.x;
    const int T = 1024;
    __shared__ float sce[DD];
    __shared__ int hist[256];
    __shared__ unsigned s_prefix;
    __shared__ int s_rem;

    int k = d_numpos[b] * 3;
    if (k > DD) k = DD;
    if (k <= 0) return;

    // stage CE slice (DD = 2183 float4 exactly)
    {
        const float4* ce4 = (const float4*)(d_ceneg + (size_t)b * DD);
        float4* s4 = (float4*)sce;
        for (int i = tid; i < DD/4; i += T) s4[i] = ce4[i];
    }
    if (tid == 0) { s_prefix = 0u; s_rem = k; }
    __syncthreads();

#pragma unroll
    for (int pass = 3; pass >= 0; pass--) {
        if (tid < 256) hist[tid] = 0;
        __syncthreads();
        const unsigned pref = s_prefix;
        const int sh = pass * 8;
        for (int d = tid; d < DD; d += T) {
            unsigned u = __float_as_uint(sce[d]);
            bool ok = (pass == 3) || ((u >> (sh + 8)) == (pref >> (sh + 8)));
            if (ok) {
                int dig = (u >> sh) & 255;
                unsigned act = __activemask();
                unsigned mm = __match_any_sync(act, dig);
                if ((int)(threadIdx.x & 31) == (__ffs(mm) - 1))
                    atomicAdd(&hist[dig], __popc(mm));
            }
        }
        __syncthreads();
        if (tid < 32) {
            const int lane = tid;
            const int base = 255 - lane*8;   // lane owns bins [base-7, base], descending
            int binv[8]; int s0 = 0;
#pragma unroll
            for (int i = 0; i < 8; i++) { binv[i] = hist[base - i]; s0 += binv[i]; }
            int pre = s0;
#pragma unroll
            for (int off = 1; off < 32; off <<= 1) {
                int o = __shfl_up_sync(0xffffffffu, pre, off);
                if (lane >= off) pre += o;
            }
            int excl = pre - s0;
            int rem = s_rem;
            bool sel = (excl < rem) && (pre >= rem);
            if (sel) {
                int cum = excl; int dg = base; int nrem = rem;
#pragma unroll
                for (int i = 0; i < 8; i++) {
                    if (cum + binv[i] >= rem) { dg = base - i; nrem = rem - cum; break; }
                    cum += binv[i];
                }
                s_prefix = pref | ((unsigned)dg << sh);
                s_rem = nrem;
            }
        }
        __syncthreads();
    }

    const unsigned uT = s_prefix;
    const float Tv = __uint_as_float(uT);
    double sg = 0.0; int cg = 0;
    for (int d = tid; d < DD; d += T) {
        float v = sce[d];
        if (__float_as_uint(v) > uT) { sg += (double)v; cg++; }
    }
#pragma unroll
    for (int s = 16; s > 0; s >>= 1) {
        sg += __shfl_down_sync(0xffffffffu, sg, s);
        cg += __shfl_down_sync(0xffffffffu, cg, s);
    }
    __shared__ double wsg[32];
    __shared__ int wcg[32];
    int wid = tid >> 5, lane = tid & 31;
    if (lane == 0) { wsg[wid] = sg; wcg[wid] = cg; }
    __syncthreads();
    if (tid == 0) {
        double tsg = 0.0; int tcg = 0;
        for (int i = 0; i < 32; i++) { tsg += wsg[i]; tcg += wcg[i]; }
        atomicAdd(&a_lossc, tsg + (double)(k - tcg) * (double)Tv);
    }
}

// Ordered compaction: positives in flat order, then earliest batch-0 negatives.
__global__ void k_compact(const float* __restrict__ line,
                          const float* __restrict__ tgt) {
    const int b = blockIdx.x, tid = threadIdx.x;
    const int CHP = (DD + 255) / 256; // 35
    int d0 = tid * CHP;
    int d1 = d0 + CHP; if (d1 > DD) d1 = DD;

    __shared__ int s_off, s_tot;
    if (tid == 0) {
        int acc = 0, off = 0;
        for (int i = 0; i < BB; i++) { if (i == b) off = acc; acc += d_numpos[i]; }
        s_off = off; s_tot = acc;
    }

    int cnt = 0;
    for (int d = d0; d < d1; d++) if ((d_ct[b*DD + d] & 31) > 0) cnt++;
    __shared__ int sc[256];
    sc[tid] = cnt;
    __syncthreads();
    if (tid == 0) {
        int acc = 0;
        for (int i = 0; i < 256; i++) { int c = sc[i]; sc[i] = acc; acc += c; }
    }
    __syncthreads();

    int rank = s_off + sc[tid];
    for (int d = d0; d < d1 && rank < KK; d++) {
        int idx = b*DD + d;
        unsigned char ct = d_ct[idx];
        int cf = ct & 31;
        if (cf > 0) {
            int slot = rank++;
            d_lab[slot] = cf;
            d_val[slot] = 1;
#pragma unroll
            for (int l = 0; l < LL; l++) d_emb[slot*LL + l] = line[(size_t)idx*LL + l];
            int t = ct >> 5;
            const float* p = tgt + (size_t)(b*OO + t)*9;
            d_qp[slot*3+0] = p[5]; d_qp[slot*3+1] = p[6]; d_qp[slot*3+2] = p[7];
        }
    }

    if (b == 0) {
        __syncthreads();
        __shared__ int smap[256];
        if (tid == 0) {
            int Pt = s_tot;
            int nr = 0;
            for (int d = 0; d < 256; d++) {
                int slot = -1;
                if ((d_ct[d] & 31) == 0) {
                    int s2 = Pt + nr; nr++;
                    if (s2 < KK) slot = s2;
                }
                smap[d] = slot;
            }
        }
        __syncthreads();
        int d = tid;
        int slot = smap[d];
        if (slot >= 0) {
            unsigned char ct = d_ct[d];
            d_lab[slot] = ct & 31;
            d_val[slot] = 0;
#pragma unroll
            for (int l = 0; l < LL; l++) d_emb[slot*LL + l] = line[(size_t)d*LL + l];
            int t = ct >> 5;
            const float* p = tgt + (size_t)t*9;
            d_qp[slot*3+0] = p[5]; d_qp[slot*3+1] = p[6]; d_qp[slot*3+2] = p[7];
        }
    }
}

// Fused pairwise + triplet. Block i (anchor), thread j (partner).
__global__ void k_pairstrip() {
    int i = blockIdx.x, j = threadIdx.x;
    __shared__ float ei[LL], ni[LL], qi[3];
    __shared__ int labi, vali;
    __shared__ float sdist[KK];
    __shared__ unsigned pm[8], nm[8];

    if (j < LL) ei[j] = d_emb[i*LL + j];
    if (j == 0) {
        labi = d_lab[i]; vali = d_val[i];
        qi[0] = d_qp[i*3+0]; qi[1] = d_qp[i*3+1]; qi[2] = d_qp[i*3+2];
    }
    __syncthreads();
    if (j == 0) {
        float s = 0.0f;
        for (int l = 0; l < LL; l++) s += ei[l]*ei[l];
        float n = fmaxf(sqrtf(s), 1e-12f);
        for (int l = 0; l < LL; l++) ni[l] = ei[l] / n;
    }
    __syncthreads();

    float ej[LL];
#pragma unroll
    for (int l = 0; l < LL; l++) ej[l] = d_emb[j*LL + l];
    float s = 0.0f;
#pragma unroll
    for (int l = 0; l < LL; l++) s += ej[l]*ej[l];
    float rnj = 1.0f / fmaxf(sqrtf(s), 1e-12f);

    float sq = 0.0f, esq = 0.0f;
#pragma unroll
    for (int l = 0; l < LL; l++) {
        float dn = ni[l] - ej[l]*rnj; sq  += dn*dn;
        float de = ei[l] - ej[l];     esq += de*de;
    }
    float dist = sqrtf(fmaxf(sq, 1e-12f));
    sdist[j] = dist;

    float qsq = 0.0f;
#pragma unroll
    for (int c = 0; c < 3; c++) { float dq = qi[c] - d_qp[j*3+c]; qsq += dq*dq; }

    bool vp   = vali && d_val[j] && (i != j);
    bool same = (labi == d_lab[j]);
    bool pp = vp &&  same && (dist > 0.2f);
    bool np = vp && !same && (dist < 0.8f);

    unsigned pb = __ballot_sync(0xffffffffu, pp);
    unsigned nb = __ballot_sync(0xffffffffu, np);
    if ((j & 31) == 0) { pm[j>>5] = pb; nm[j>>5] = nb; }

    double dk = pp ? (double)((esq - qsq) * (esq - qsq)) : 0.0;
    int cp = pp ? 1 : 0, cn = np ? 1 : 0;
#pragma unroll
    for (int st = 16; st > 0; st >>= 1) {
        dk += __shfl_down_sync(0xffffffffu, dk, st);
        cp += __shfl_down_sync(0xffffffffu, cp, st);
        cn += __shfl_down_sync(0xffffffffu, cn, st);
    }
    __shared__ double wdk[8];
    __shared__ int wcp[8], wcn[8];
    int wid = j >> 5, lane = j & 31;
    if (lane == 0) { wdk[wid] = dk; wcp[wid] = cp; wcn[wid] = cn; }
    __syncthreads();
    if (j == 0) {
        double t = 0.0; int p = 0, n = 0;
        for (int w = 0; w < 8; w++) { t += wdk[w]; p += wcp[w]; n += wcn[w]; }
        if (t != 0.0) atomicAdd(&a_desk, t);
        if (p) atomicAdd(&a_npp, (unsigned long long)p);
        if (n) atomicAdd(&a_nnp, (unsigned long long)n);
    }

    __shared__ int pj[KK];
    __shared__ int npj;
    if (j == 0) {
        int n = 0;
        for (int w = 0; w < 8; w++) {
            unsigned m = pm[w];
            while (m) { int bp = __ffs(m) - 1; pj[n++] = w*32 + bp; m &= (m - 1); }
        }
        npj = n;
    }
    __syncthreads();
    int n = npj;
    if (n == 0) return;

    bool isneg = (nm[j >> 5] >> (j & 31)) & 1u;
    double ls = 0.0;
    int lc = 0;
    if (isneg) {
        float dk2 = sdist[j];
        for (int a = 0; a < n; a++) {
            float l = sdist[pj[a]] - dk2 + 0.2f;
            if (l > 0.0f) { ls += (double)l; lc++; }
        }
    }
#pragma unroll
    for (int st = 16; st > 0; st >>= 1) {
        ls += __shfl_down_sync(0xffffffffu, ls, st);
        lc += __shfl_down_sync(0xffffffffu, lc, st);
    }
    __shared__ double wls[8];
    __shared__ int wlc[8];
    if (lane == 0) { wls[wid] = ls; wlc[wid] = lc; }
    __syncthreads();
    if (j == 0) {
        double t = 0.0; unsigned long long c = 0ull;
        for (int w = 0; w < 8; w++) { t += wls[w]; c += (unsigned long long)wlc[w]; }
        if (t != 0.0 || c != 0ull) {
            atomicAdd(&a_trips, t);
            atomicAdd(&a_tripc, c);
        }
    }
}

__global__ void k_final(float* __restrict__ out) {
    if (threadIdx.x == 0 && blockIdx.x == 0) {
        double N = 0.0;
        for (int b = 0; b < BB; b++) N += (double)d_numpos[b];
        if (N < 1.0) N = 1.0;
        double lossl = a_lossl / N;
        double lossc = a_lossc / N;
        double lossp = a_lossp / N;

        unsigned long long npp = a_npp;
        double dnpp = (npp < 1ull) ? 1.0 : (double)npp;
        unsigned long long tc = a_tripc;
        double losst = a_trips / (double)((tc < 1ull) ? 1ull : tc);
        unsigned long long pn = a_npp + a_nnp;
        double dpn = (pn < 1ull) ? 1.0 : (double)pn;

        double ldesk = a_desk / dnpp + losst / dpn;
        ldesk = ldesk / dnpp / 32.0;

        out[0] = (float)lossl;
        out[1] = (float)lossc;
        out[2] = (float)lossp;
        out[3] = (float)ldesk;
        out[4] = (float)losst;
    }
}

// ---------------- host launcher ----------------
extern "C" void kernel_launch(void* const* d_in, const int* in_sizes, int n_in,
                              void* d_out, int out_size) {
    const float *loc = 0, *conf = 0, *line = 0, *pose = 0, *dbox = 0, *tgt = 0;
    for (int i = 0; i < n_in; i++) {
        switch (in_sizes[i]) {
            case BB*DD*4:  loc  = (const float*)d_in[i]; break;
            case BB*DD*CC: conf = (const float*)d_in[i]; break;
            case BB*DD*LL: line = (const float*)d_in[i]; break;
            case BB*DD*3:  pose = (const float*)d_in[i]; break;
            case DD*4:     dbox = (const float*)d_in[i]; break;
            case BB*OO*9:  tgt  = (const float*)d_in[i]; break;
            default: break;
        }
    }
    if (!loc)  loc  = (const float*)d_in[0];
    if (!conf) conf = (const float*)d_in[1];
    if (!line) line = (const float*)d_in[2];
    if (!pose) pose = (const float*)d_in[3];
    if (!dbox) dbox = (const float*)d_in[4];
    if (!tgt)  tgt  = (const float*)d_in[5];

    k_init<<<1, 256>>>();
    k_match1<<<dim3(NCH, BB), 256>>>(dbox, tgt);
    k_encce<<<dim3((DD + 255) / 256, BB), 256>>>(loc, pose, dbox, tgt, conf);
    k_topk<<<BB, 1024>>>();
    k_compact<<<BB, 256>>>(line, tgt);
    k_pairstrip<<<KK, 256>>>();
    k_final<<<1, 1>>>((float*)d_out);
}